// round 3
// baseline (speedup 1.0000x reference)
#include <cuda_runtime.h>
#include <math.h>

// Problem constants
#define BB   2
#define SEQ  2048
#define DIM  768
#define NH   12
#define HD   64
#define NN   (SEQ * SEQ)   // 4194304

// Scratch (device globals: allocation-guard safe)
__device__ float g_Q[(size_t)BB * SEQ * DIM];
__device__ float g_K[(size_t)BB * SEQ * DIM];
__device__ float g_V[(size_t)BB * SEQ * DIM];
__device__ float g_S[(size_t)BB * NH * SEQ * SEQ];   // 402 MB scores/attn

// ---------------------------------------------------------------------------
// Tiled GEMM, C = A * B^T  (A: M x K row-major w/ lda; B: N x K row-major w/ ldb)
// 64x64 tile, BK=16, 256 threads, 4x4 microtile. Batched via blockIdx.z with
// two-level (batch, head) offsets: off = (z/NH)*bs + (z%NH)*hs.
// All dims used here divide the tile sizes exactly -> no bounds checks.
// ---------------------------------------------------------------------------
__global__ void gemm_nt(const float* __restrict__ A, const float* __restrict__ B,
                        float* __restrict__ C,
                        int M, int N, int K, int lda, int ldb, int ldc,
                        long bsA, long hsA, long bsB, long hsB, long bsC, long hsC)
{
    const int z = blockIdx.z;
    const int bb = z / NH, hh = z % NH;
    A += (long)bb * bsA + (long)hh * hsA;
    B += (long)bb * bsB + (long)hh * hsB;
    C += (long)bb * bsC + (long)hh * hsC;

    __shared__ float As[16][64];
    __shared__ float Bs[16][64];

    const int tid = threadIdx.x;
    const int m0 = blockIdx.y * 64;
    const int n0 = blockIdx.x * 64;
    const int tx = tid & 15;   // n direction
    const int ty = tid >> 4;   // m direction

    float acc[4][4] = {};

    const int lr = tid >> 2;          // 0..63 row within tile
    const int lk = (tid & 3) * 4;     // 0,4,8,12 within BK

    for (int k0 = 0; k0 < K; k0 += 16) {
        float4 va = *(const float4*)&A[(long)(m0 + lr) * lda + k0 + lk];
        float4 vb = *(const float4*)&B[(long)(n0 + lr) * ldb + k0 + lk];
        As[lk + 0][lr] = va.x; As[lk + 1][lr] = va.y;
        As[lk + 2][lr] = va.z; As[lk + 3][lr] = va.w;
        Bs[lk + 0][lr] = vb.x; Bs[lk + 1][lr] = vb.y;
        Bs[lk + 2][lr] = vb.z; Bs[lk + 3][lr] = vb.w;
        __syncthreads();

        #pragma unroll
        for (int kk = 0; kk < 16; kk++) {
            float a[4], b[4];
            #pragma unroll
            for (int i = 0; i < 4; i++) a[i] = As[kk][ty * 4 + i];
            #pragma unroll
            for (int j = 0; j < 4; j++) b[j] = Bs[kk][tx * 4 + j];
            #pragma unroll
            for (int i = 0; i < 4; i++)
                #pragma unroll
                for (int j = 0; j < 4; j++)
                    acc[i][j] = fmaf(a[i], b[j], acc[i][j]);
        }
        __syncthreads();
    }

    #pragma unroll
    for (int i = 0; i < 4; i++)
        #pragma unroll
        for (int j = 0; j < 4; j++)
            C[(long)(m0 + ty * 4 + i) * ldc + n0 + tx * 4 + j] = acc[i][j];
}

// ---------------------------------------------------------------------------
// Tiled GEMM, C = A * B  (A: M x K row-major; B: K x N row-major)
// Same tiling; only the B tile load differs.
// ---------------------------------------------------------------------------
__global__ void gemm_nn(const float* __restrict__ A, const float* __restrict__ B,
                        float* __restrict__ C,
                        int M, int N, int K, int lda, int ldb, int ldc,
                        long bsA, long hsA, long bsB, long hsB, long bsC, long hsC)
{
    const int z = blockIdx.z;
    const int bb = z / NH, hh = z % NH;
    A += (long)bb * bsA + (long)hh * hsA;
    B += (long)bb * bsB + (long)hh * hsB;
    C += (long)bb * bsC + (long)hh * hsC;

    __shared__ float As[16][64];
    __shared__ float Bs[16][64];

    const int tid = threadIdx.x;
    const int m0 = blockIdx.y * 64;
    const int n0 = blockIdx.x * 64;
    const int tx = tid & 15;
    const int ty = tid >> 4;

    float acc[4][4] = {};

    const int lr = tid >> 2;          // 0..63
    const int lk = (tid & 3) * 4;     // 0,4,8,12
    const int bk = tid >> 4;          // 0..15 (B tile row)
    const int bn = (tid & 15) * 4;    // 0..60 (B tile col)

    for (int k0 = 0; k0 < K; k0 += 16) {
        float4 va = *(const float4*)&A[(long)(m0 + lr) * lda + k0 + lk];
        As[lk + 0][lr] = va.x; As[lk + 1][lr] = va.y;
        As[lk + 2][lr] = va.z; As[lk + 3][lr] = va.w;
        float4 vb = *(const float4*)&B[(long)(k0 + bk) * ldb + n0 + bn];
        Bs[bk][bn + 0] = vb.x; Bs[bk][bn + 1] = vb.y;
        Bs[bk][bn + 2] = vb.z; Bs[bk][bn + 3] = vb.w;
        __syncthreads();

        #pragma unroll
        for (int kk = 0; kk < 16; kk++) {
            float a[4], b[4];
            #pragma unroll
            for (int i = 0; i < 4; i++) a[i] = As[kk][ty * 4 + i];
            #pragma unroll
            for (int j = 0; j < 4; j++) b[j] = Bs[kk][tx * 4 + j];
            #pragma unroll
            for (int i = 0; i < 4; i++)
                #pragma unroll
                for (int j = 0; j < 4; j++)
                    acc[i][j] = fmaf(a[i], b[j], acc[i][j]);
        }
        __syncthreads();
    }

    #pragma unroll
    for (int i = 0; i < 4; i++)
        #pragma unroll
        for (int j = 0; j < 4; j++)
            C[(long)(m0 + ty * 4 + i) * ldc + n0 + tx * 4 + j] = acc[i][j];
}

// ---------------------------------------------------------------------------
// Softmax over the HEADS axis (12 values, stride NN apart), then * 1/sqrt(768).
// One thread per (b, q, k). In-place on g_S.
// ---------------------------------------------------------------------------
__global__ void softmax_heads(float* __restrict__ S)
{
    long idx = (long)blockIdx.x * blockDim.x + threadIdx.x;
    if (idx >= (long)BB * NN) return;
    long b = idx / NN;
    long r = idx % NN;
    float* p = S + b * (long)NH * NN + r;

    float v[NH];
    float m = -1e30f;
    #pragma unroll
    for (int h = 0; h < NH; h++) {
        v[h] = p[(long)h * NN];
        m = fmaxf(m, v[h]);
    }
    float s = 0.f;
    #pragma unroll
    for (int h = 0; h < NH; h++) {
        v[h] = __expf(v[h] - m);
        s += v[h];
    }
    const float inv = 0.03608439182435161f / s;   // (1/sqrt(768)) / sum
    #pragma unroll
    for (int h = 0; h < NH; h++)
        p[(long)h * NN] = v[h] * inv;
}

extern "C" void kernel_launch(void* const* d_in, const int* in_sizes, int n_in,
                              void* d_out, int out_size)
{
    const float* x  = (const float*)d_in[0];
    const float* Wq = (const float*)d_in[1];
    const float* Wk = (const float*)d_in[2];
    const float* Wv = (const float*)d_in[3];
    float* out = (float*)d_out;

    float *Q, *K, *V, *S;
    cudaGetSymbolAddress((void**)&Q, g_Q);
    cudaGetSymbolAddress((void**)&K, g_K);
    cudaGetSymbolAddress((void**)&V, g_V);
    cudaGetSymbolAddress((void**)&S, g_S);

    dim3 blk(256);

    // 1) Projections: (4096 x 768) = x(4096 x 768) @ W^T(768 x 768)
    {
        dim3 grid(DIM / 64, (BB * SEQ) / 64, 1);
        gemm_nt<<<grid, blk>>>(x, Wq, Q, BB * SEQ, DIM, DIM, DIM, DIM, DIM,
                               0, 0, 0, 0, 0, 0);
        gemm_nt<<<grid, blk>>>(x, Wk, K, BB * SEQ, DIM, DIM, DIM, DIM, DIM,
                               0, 0, 0, 0, 0, 0);
        gemm_nt<<<grid, blk>>>(x, Wv, V, BB * SEQ, DIM, DIM, DIM, DIM, DIM,
                               0, 0, 0, 0, 0, 0);
    }

    // 2) Scores: per (b,h) S[q,k] = Q_h[q,:] . K_h[k,:]   (M=N=2048, K=64)
    {
        dim3 grid(SEQ / 64, SEQ / 64, BB * NH);
        gemm_nt<<<grid, blk>>>(Q, K, S, SEQ, SEQ, HD, DIM, DIM, SEQ,
                               (long)SEQ * DIM, HD,
                               (long)SEQ * DIM, HD,
                               (long)NH * NN,   NN);
    }

    // 3) Softmax over heads + scale (in place on S)
    {
        long total = (long)BB * NN;
        int nblk = (int)((total + 255) / 256);
        softmax_heads<<<nblk, blk>>>(S);
    }

    // 4) Out: per (b,h) O[q,d] = sum_k P[q,k] * V_h[k,d]   (M=2048, N=64, K=2048)
    {
        dim3 grid(HD / 64, SEQ / 64, BB * NH);
        gemm_nn<<<grid, blk>>>(S, V, out, SEQ, HD, SEQ, SEQ, DIM, DIM,
                               (long)NH * NN,   NN,
                               (long)SEQ * DIM, HD,
                               (long)SEQ * DIM, HD);
    }
}

// round 7
// speedup vs baseline: 1.3780x; 1.3780x over previous
#include <cuda_runtime.h>
#include <math.h>

#define BB   2
#define SEQ  2048
#define DIM  768
#define NH   12
#define HD   64
#define NN   (SEQ * SEQ)

// Scratch (device globals: allocation-guard safe)
__device__ float g_Q[(size_t)BB * SEQ * DIM];
__device__ float g_K[(size_t)BB * SEQ * DIM];
__device__ float g_V[(size_t)BB * SEQ * DIM];
__device__ float g_S[(size_t)BB * NH * SEQ * SEQ];

// ---------------------------------------------------------------------------
// Core NT GEMM body: C(MxN) = A(MxK,row,lda) * B(NxK,row,ldb)^T
// 128x128 tile, BK=16, 256 threads, 8x8 microtile, float4 LDS reads.
// smem loads: 16 floats / 64 FMA = 1 B/FMA  (balanced vs 128B/cyc : 128FMA/cyc)
// ---------------------------------------------------------------------------
__device__ __forceinline__ void gemm_nt_body_128(
    const float* __restrict__ A, const float* __restrict__ B, float* __restrict__ C,
    int K, int lda, int ldb, int ldc)
{
    __shared__ float As[16][132];   // pad 132 = 4*33: float4-aligned, spreads banks
    __shared__ float Bs[16][132];

    const int tid = threadIdx.x;
    const int m0 = blockIdx.y * 128;
    const int n0 = blockIdx.x * 128;
    const int tx = tid & 15;        // col group
    const int ty = tid >> 4;        // row group
    const int lrow = tid >> 1;      // 0..127 tile row for loads
    const int lk   = (tid & 1) * 8; // 0 or 8

    float acc[8][8] = {};

    for (int k0 = 0; k0 < K; k0 += 16) {
        float4 va0 = *(const float4*)&A[(long)(m0 + lrow) * lda + k0 + lk];
        float4 va1 = *(const float4*)&A[(long)(m0 + lrow) * lda + k0 + lk + 4];
        float4 vb0 = *(const float4*)&B[(long)(n0 + lrow) * ldb + k0 + lk];
        float4 vb1 = *(const float4*)&B[(long)(n0 + lrow) * ldb + k0 + lk + 4];
        As[lk + 0][lrow] = va0.x; As[lk + 1][lrow] = va0.y;
        As[lk + 2][lrow] = va0.z; As[lk + 3][lrow] = va0.w;
        As[lk + 4][lrow] = va1.x; As[lk + 5][lrow] = va1.y;
        As[lk + 6][lrow] = va1.z; As[lk + 7][lrow] = va1.w;
        Bs[lk + 0][lrow] = vb0.x; Bs[lk + 1][lrow] = vb0.y;
        Bs[lk + 2][lrow] = vb0.z; Bs[lk + 3][lrow] = vb0.w;
        Bs[lk + 4][lrow] = vb1.x; Bs[lk + 5][lrow] = vb1.y;
        Bs[lk + 6][lrow] = vb1.z; Bs[lk + 7][lrow] = vb1.w;
        __syncthreads();

        #pragma unroll
        for (int kk = 0; kk < 16; kk++) {
            float4 a0 = *(const float4*)&As[kk][ty * 4];
            float4 a1 = *(const float4*)&As[kk][64 + ty * 4];
            float4 b0 = *(const float4*)&Bs[kk][tx * 4];
            float4 b1 = *(const float4*)&Bs[kk][64 + tx * 4];
            float a[8] = {a0.x, a0.y, a0.z, a0.w, a1.x, a1.y, a1.z, a1.w};
            float b[8] = {b0.x, b0.y, b0.z, b0.w, b1.x, b1.y, b1.z, b1.w};
            #pragma unroll
            for (int i = 0; i < 8; i++)
                #pragma unroll
                for (int j = 0; j < 8; j++)
                    acc[i][j] = fmaf(a[i], b[j], acc[i][j]);
        }
        __syncthreads();
    }

    #pragma unroll
    for (int i = 0; i < 8; i++) {
        int row = m0 + ((i < 4) ? (ty * 4 + i) : (64 + ty * 4 + i - 4));
        float4 c0 = {acc[i][0], acc[i][1], acc[i][2], acc[i][3]};
        float4 c1 = {acc[i][4], acc[i][5], acc[i][6], acc[i][7]};
        *(float4*)&C[(long)row * ldc + n0 + tx * 4]      = c0;
        *(float4*)&C[(long)row * ldc + n0 + 64 + tx * 4] = c1;
    }
}

// Fused QKV projection: z = 0/1/2 selects Wq/Wk/Wv and Q/K/V. y = x @ W^T.
__global__ __launch_bounds__(256) void proj_kernel(
    const float* __restrict__ x,
    const float* __restrict__ Wq, const float* __restrict__ Wk, const float* __restrict__ Wv,
    float* __restrict__ Q, float* __restrict__ K, float* __restrict__ V)
{
    const int z = blockIdx.z;
    const float* W = (z == 0) ? Wq : (z == 1) ? Wk : Wv;
    float* O       = (z == 0) ? Q  : (z == 1) ? K  : V;
    gemm_nt_body_128(x, W, O, DIM, DIM, DIM, DIM);
}

// Scores: per (b,h)  S[q,k] = Q_h[q,:] . K_h[k,:]
__global__ __launch_bounds__(256) void scores_kernel(
    const float* __restrict__ Q, const float* __restrict__ Kp, float* __restrict__ S)
{
    const int z = blockIdx.z;
    const int bb = z / NH, hh = z % NH;
    const float* A = Q  + (long)bb * SEQ * DIM + (long)hh * HD;
    const float* B = Kp + (long)bb * SEQ * DIM + (long)hh * HD;
    float* C = S + (long)z * NN;
    gemm_nt_body_128(A, B, C, HD, DIM, DIM, SEQ);
}

// ---------------------------------------------------------------------------
// Softmax over HEADS axis (stride NN), then * 1/sqrt(768). float4-vectorized.
// ---------------------------------------------------------------------------
__global__ __launch_bounds__(256) void softmax_heads(float* __restrict__ S)
{
    long t = (long)blockIdx.x * blockDim.x + threadIdx.x;       // 4 elems each
    const long per_b = NN / 4;
    long b = t / per_b;
    long r = (t % per_b) * 4;
    float* p = S + b * (long)NH * NN + r;

    float4 v[NH];
    float4 m = {-1e30f, -1e30f, -1e30f, -1e30f};
    #pragma unroll
    for (int h = 0; h < NH; h++) {
        v[h] = *(const float4*)(p + (long)h * NN);
        m.x = fmaxf(m.x, v[h].x); m.y = fmaxf(m.y, v[h].y);
        m.z = fmaxf(m.z, v[h].z); m.w = fmaxf(m.w, v[h].w);
    }
    float4 s = {0.f, 0.f, 0.f, 0.f};
    #pragma unroll
    for (int h = 0; h < NH; h++) {
        v[h].x = __expf(v[h].x - m.x); s.x += v[h].x;
        v[h].y = __expf(v[h].y - m.y); s.y += v[h].y;
        v[h].z = __expf(v[h].z - m.z); s.z += v[h].z;
        v[h].w = __expf(v[h].w - m.w); s.w += v[h].w;
    }
    const float c = 0.03608439182435161f;  // 1/sqrt(768)
    float4 inv = {c / s.x, c / s.y, c / s.z, c / s.w};
    #pragma unroll
    for (int h = 0; h < NH; h++) {
        float4 o = {v[h].x * inv.x, v[h].y * inv.y, v[h].z * inv.z, v[h].w * inv.w};
        *(float4*)(p + (long)h * NN) = o;
    }
}

// ---------------------------------------------------------------------------
// AV GEMM (NN): per (b,h)  O[q,d] = sum_k P[q,k] * V_h[k,d]
// M=2048, N=64, K=2048. 64x64 tile, 64 threads, 8x8 microtile (1 B/FMA).
// grid (1, 32, 24) = 768 blocks ~ 5/SM, single balanced wave.
// ---------------------------------------------------------------------------
__global__ __launch_bounds__(64) void av_kernel(
    const float* __restrict__ S, const float* __restrict__ V, float* __restrict__ O)
{
    const int z = blockIdx.z;
    const int bb = z / NH, hh = z % NH;
    const float* A = S + (long)z * NN;                               // lda = SEQ
    const float* B = V + (long)bb * SEQ * DIM + (long)hh * HD;       // ldb = DIM
    float* C       = O + (long)bb * SEQ * DIM + (long)hh * HD;       // ldc = DIM

    __shared__ float As[16][68];
    __shared__ float Bs[16][68];

    const int tid = threadIdx.x;
    const int m0 = blockIdx.y * 64;
    const int tx = tid & 7;
    const int ty = tid >> 3;
    const int bk = tid >> 2;            // 0..15
    const int bn = (tid & 3) * 16;      // 0,16,32,48

    float acc[8][8] = {};

    for (int k0 = 0; k0 < SEQ; k0 += 16) {
        // A tile: 64 rows x 16 k ; one row per thread, 4 float4 along k
        {
            const float* ap = &A[(long)(m0 + tid) * SEQ + k0];
            float4 v0 = *(const float4*)(ap + 0);
            float4 v1 = *(const float4*)(ap + 4);
            float4 v2 = *(const float4*)(ap + 8);
            float4 v3 = *(const float4*)(ap + 12);
            As[0][tid]  = v0.x; As[1][tid]  = v0.y; As[2][tid]  = v0.z; As[3][tid]  = v0.w;
            As[4][tid]  = v1.x; As[5][tid]  = v1.y; As[6][tid]  = v1.z; As[7][tid]  = v1.w;
            As[8][tid]  = v2.x; As[9][tid]  = v2.y; As[10][tid] = v2.z; As[11][tid] = v2.w;
            As[12][tid] = v3.x; As[13][tid] = v3.y; As[14][tid] = v3.z; As[15][tid] = v3.w;
        }
        // B tile: 16 k x 64 n ; thread loads 16 consecutive n for one k
        {
            const float* bp = &B[(long)(k0 + bk) * DIM + bn];
            float4 v0 = *(const float4*)(bp + 0);
            float4 v1 = *(const float4*)(bp + 4);
            float4 v2 = *(const float4*)(bp + 8);
            float4 v3 = *(const float4*)(bp + 12);
            *(float4*)&Bs[bk][bn + 0]  = v0;
            *(float4*)&Bs[bk][bn + 4]  = v1;
            *(float4*)&Bs[bk][bn + 8]  = v2;
            *(float4*)&Bs[bk][bn + 12] = v3;
        }
        __syncthreads();

        #pragma unroll
        for (int kk = 0; kk < 16; kk++) {
            float4 a0 = *(const float4*)&As[kk][ty * 4];
            float4 a1 = *(const float4*)&As[kk][32 + ty * 4];
            float4 b0 = *(const float4*)&Bs[kk][tx * 4];
            float4 b1 = *(const float4*)&Bs[kk][32 + tx * 4];
            float a[8] = {a0.x, a0.y, a0.z, a0.w, a1.x, a1.y, a1.z, a1.w};
            float b[8] = {b0.x, b0.y, b0.z, b0.w, b1.x, b1.y, b1.z, b1.w};
            #pragma unroll
            for (int i = 0; i < 8; i++)
                #pragma unroll
                for (int j = 0; j < 8; j++)
                    acc[i][j] = fmaf(a[i], b[j], acc[i][j]);
        }
        __syncthreads();
    }

    #pragma unroll
    for (int i = 0; i < 8; i++) {
        int row = m0 + ((i < 4) ? (ty * 4 + i) : (32 + ty * 4 + i - 4));
        float4 c0 = {acc[i][0], acc[i][1], acc[i][2], acc[i][3]};
        float4 c1 = {acc[i][4], acc[i][5], acc[i][6], acc[i][7]};
        *(float4*)&C[(long)row * DIM + tx * 4]      = c0;
        *(float4*)&C[(long)row * DIM + 32 + tx * 4] = c1;
    }
}

extern "C" void kernel_launch(void* const* d_in, const int* in_sizes, int n_in,
                              void* d_out, int out_size)
{
    const float* x  = (const float*)d_in[0];
    const float* Wq = (const float*)d_in[1];
    const float* Wk = (const float*)d_in[2];
    const float* Wv = (const float*)d_in[3];
    float* out = (float*)d_out;

    float *Q, *K, *V, *S;
    cudaGetSymbolAddress((void**)&Q, g_Q);
    cudaGetSymbolAddress((void**)&K, g_K);
    cudaGetSymbolAddress((void**)&V, g_V);
    cudaGetSymbolAddress((void**)&S, g_S);

    // 1) QKV projections, one fused launch: grid (768/128, 4096/128, 3)
    {
        dim3 grid(DIM / 128, (BB * SEQ) / 128, 3);
        proj_kernel<<<grid, 256>>>(x, Wq, Wk, Wv, Q, K, V);
    }
    // 2) Scores: grid (16, 16, 24)
    {
        dim3 grid(SEQ / 128, SEQ / 128, BB * NH);
        scores_kernel<<<grid, 256>>>(Q, K, S);
    }
    // 3) Softmax over heads (float4: 4 elems/thread)
    {
        long threads = (long)BB * NN / 4;
        softmax_heads<<<(int)(threads / 256), 256>>>(S);
    }
    // 4) AV: grid (1, 32, 24)
    {
        dim3 grid(1, SEQ / 64, BB * NH);
        av_kernel<<<grid, 64>>>(S, V, out);
    }
}